// round 4
// baseline (speedup 1.0000x reference)
#include <cuda_runtime.h>
#include <cuda_bf16.h>

#define NNODE 50000
#define EDGES 600000
#define NGRAPH 500
#define NPG 100
#define KSEL 30
#define FIN 128
#define D 64
#define DT 129

typedef unsigned long long u64;

__device__ __forceinline__ u64 pack2(float lo, float hi) {
    u64 r;
    asm("mov.b64 %0, {%1, %2};" : "=l"(r) : "r"(__float_as_uint(lo)), "r"(__float_as_uint(hi)));
    return r;
}
__device__ __forceinline__ u64 dup2(float v) {
    u64 r;
    asm("mov.b64 %0, {%1, %1};" : "=l"(r) : "r"(__float_as_uint(v)));
    return r;
}
__device__ __forceinline__ void fma2(u64& acc, u64 a, u64 b) {
    asm("fma.rn.f32x2 %0, %1, %2, %0;" : "+l"(acc) : "l"(a), "l"(b));
}

// ---------------- scratch ----------------
__device__ float g_dinv[NNODE];
__device__ int   g_cnt[NNODE];          // zero at call start (atomicSub restores)
__device__ int   g_off[NNODE + 1];
__device__ int   g_csrc[EDGES];
__device__ float g_H[NNODE * D];
__device__ float g_h[NNODE * D];
__device__ float g_s0[NNODE];
__device__ float g_u[NNODE];
__device__ float g_h3[NNODE];
__device__ float g_x1[NNODE * D];
__device__ float g_x2[NNODE * D];

// ---------------- setup ----------------
__global__ void k_count(const int* __restrict__ ei) {
    int e = blockIdx.x * blockDim.x + threadIdx.x;
    if (e >= EDGES) return;
    atomicAdd(&g_cnt[ei[EDGES + e]], 1);
}

__global__ void k_scan_dinv() {
    __shared__ int wsum[32];
    const int PER = 49;
    int t = threadIdx.x;
    int base = t * PER;
    int local = 0;
    for (int k = 0; k < PER; k++) {
        int idx = base + k;
        if (idx < NNODE) local += g_cnt[idx];
    }
    int lane = t & 31, w = t >> 5;
    int v = local;
#pragma unroll
    for (int o = 1; o < 32; o <<= 1) {
        int n = __shfl_up_sync(0xffffffffu, v, o);
        if (lane >= o) v += n;
    }
    if (lane == 31) wsum[w] = v;
    __syncthreads();
    if (w == 0) {
        int s = wsum[lane];
#pragma unroll
        for (int o = 1; o < 32; o <<= 1) {
            int n = __shfl_up_sync(0xffffffffu, s, o);
            if (lane >= o) s += n;
        }
        wsum[lane] = s;
    }
    __syncthreads();
    int run = v - local + (w > 0 ? wsum[w - 1] : 0);
    for (int k = 0; k < PER; k++) {
        int idx = base + k;
        if (idx < NNODE) {
            int c = g_cnt[idx];
            g_off[idx] = run;
            run += c;
            g_dinv[idx] = rsqrtf((float)c + 1.0f);
        }
    }
    if (t == 1023) g_off[NNODE] = EDGES;
}

__global__ void k_fill(const int* __restrict__ ei) {
    int e = blockIdx.x * blockDim.x + threadIdx.x;
    if (e >= EDGES) return;
    int s = ei[e];
    int d = ei[EDGES + e];
    int p = atomicSub(&g_cnt[d], 1) - 1;
    g_csrc[g_off[d] + p] = s;
}

// ---------------- SGEMM (f32x2): out[N,64] = X[N,K] @ W[K,64] ----------------
template <int K>
__global__ void __launch_bounds__(128) k_gemm(const float* __restrict__ X,
                                              const float* __restrict__ W,
                                              float* __restrict__ out) {
    __shared__ float Xt[16][136];
    __shared__ float Wsm[16][64];
    int tid = threadIdx.x;
    int rb = blockIdx.x * 128;
    int tx = tid & 7;
    int ty = tid >> 3;
    u64 acc2[8][4];
#pragma unroll
    for (int r = 0; r < 8; r++)
#pragma unroll
        for (int c = 0; c < 4; c++) acc2[r][c] = 0ULL;
#pragma unroll 1
    for (int k0 = 0; k0 < K; k0 += 16) {
        {
            int gr = rb + tid;
            float4 v0, v1, v2, v3;
            if (gr < NNODE) {
                const float4* xp = (const float4*)(X + (size_t)gr * K + k0);
                v0 = xp[0]; v1 = xp[1]; v2 = xp[2]; v3 = xp[3];
            } else {
                v0 = v1 = v2 = v3 = make_float4(0.f, 0.f, 0.f, 0.f);
            }
            Xt[0][tid] = v0.x;  Xt[1][tid] = v0.y;  Xt[2][tid] = v0.z;  Xt[3][tid] = v0.w;
            Xt[4][tid] = v1.x;  Xt[5][tid] = v1.y;  Xt[6][tid] = v1.z;  Xt[7][tid] = v1.w;
            Xt[8][tid] = v2.x;  Xt[9][tid] = v2.y;  Xt[10][tid] = v2.z; Xt[11][tid] = v2.w;
            Xt[12][tid] = v3.x; Xt[13][tid] = v3.y; Xt[14][tid] = v3.z; Xt[15][tid] = v3.w;
        }
#pragma unroll
        for (int i = 0; i < 2; i++) {
            int f = tid + i * 128;
            int kk = f >> 4, c4 = f & 15;
            *(float4*)&Wsm[kk][c4 * 4] = *(const float4*)(W + (size_t)(k0 + kk) * 64 + c4 * 4);
        }
        __syncthreads();
#pragma unroll
        for (int kk = 0; kk < 16; kk++) {
            float a[8];
            *(float4*)&a[0] = *(const float4*)&Xt[kk][ty * 8];
            *(float4*)&a[4] = *(const float4*)&Xt[kk][ty * 8 + 4];
            u64 b2[4];
            const u64* bp = (const u64*)&Wsm[kk][tx * 8];
            b2[0] = bp[0]; b2[1] = bp[1]; b2[2] = bp[2]; b2[3] = bp[3];
#pragma unroll
            for (int r = 0; r < 8; r++) {
                u64 ar = dup2(a[r]);
#pragma unroll
                for (int c = 0; c < 4; c++) fma2(acc2[r][c], ar, b2[c]);
            }
        }
        __syncthreads();
    }
#pragma unroll
    for (int r = 0; r < 8; r++) {
        int gr = rb + ty * 8 + r;
        if (gr < NNODE) {
            float2 p0 = *(float2*)&acc2[r][0];
            float2 p1 = *(float2*)&acc2[r][1];
            float2 p2 = *(float2*)&acc2[r][2];
            float2 p3 = *(float2*)&acc2[r][3];
            float4* op = (float4*)(out + (size_t)gr * 64 + tx * 8);
            op[0] = make_float4(p0.x, p0.y, p1.x, p1.y);
            op[1] = make_float4(p2.x, p2.y, p3.x, p3.y);
        }
    }
}

// ---------------- 64-wide GCN aggregation + fused dots (f32x2) ----------------
__global__ void k_agg64f(const float* __restrict__ Hin, const float* __restrict__ bias,
                         const float* __restrict__ Wg, const float* __restrict__ Wu,
                         float* __restrict__ out, float* __restrict__ sg,
                         float* __restrict__ su) {
    int warp = (blockIdx.x * blockDim.x + threadIdx.x) >> 5;
    int lane = threadIdx.x & 31;
    if (warp >= NNODE) return;
    int i = warp;
    float di = g_dinv[i];
    float di2 = di * di;
    const u64* Hu = (const u64*)Hin;
    float2 self = ((const float2*)Hin)[i * 32 + lane];
    float2 bv = ((const float2*)bias)[lane];
    u64 acc = pack2(fmaf(self.x, di2, bv.x), fmaf(self.y, di2, bv.y));
    int j = g_off[i], e1 = g_off[i + 1];
    for (; j + 4 <= e1; j += 4) {
        int s0 = __ldg(&g_csrc[j]);
        int s1 = __ldg(&g_csrc[j + 1]);
        int s2 = __ldg(&g_csrc[j + 2]);
        int s3 = __ldg(&g_csrc[j + 3]);
        u64 v0 = __ldg(&Hu[s0 * 32 + lane]);
        u64 v1 = __ldg(&Hu[s1 * 32 + lane]);
        u64 v2 = __ldg(&Hu[s2 * 32 + lane]);
        u64 v3 = __ldg(&Hu[s3 * 32 + lane]);
        fma2(acc, v0, dup2(g_dinv[s0] * di));
        fma2(acc, v1, dup2(g_dinv[s1] * di));
        fma2(acc, v2, dup2(g_dinv[s2] * di));
        fma2(acc, v3, dup2(g_dinv[s3] * di));
    }
    for (; j < e1; j++) {
        int s = __ldg(&g_csrc[j]);
        u64 v = __ldg(&Hu[s * 32 + lane]);
        fma2(acc, v, dup2(g_dinv[s] * di));
    }
    float2 av = *(float2*)&acc;
    float ax = fmaxf(av.x, 0.f);
    float ay = fmaxf(av.y, 0.f);
    ((float2*)out)[i * 32 + lane] = make_float2(ax, ay);
    float2 wg = ((const float2*)Wg)[lane];
    float dg = ax * wg.x + ay * wg.y;
#pragma unroll
    for (int o = 16; o; o >>= 1) dg += __shfl_xor_sync(0xffffffffu, dg, o);
    if (lane == 0) sg[i] = dg;
    if (Wu) {
        float2 wu = ((const float2*)Wu)[lane];
        float du = ax * wu.x + ay * wu.y;
#pragma unroll
        for (int o = 16; o; o >>= 1) du += __shfl_xor_sync(0xffffffffu, du, o);
        if (lane == 0) su[i] = du;
    }
}

// ---------------- gate (layer 1): 8 lanes per node ----------------
__global__ void k_gate(const float* __restrict__ s0, const float* __restrict__ h,
                       const float* __restrict__ bias, float* __restrict__ dst) {
    int gt = blockIdx.x * blockDim.x + threadIdx.x;
    int i = gt >> 3;
    int sub = threadIdx.x & 7;
    if (i >= NNODE) return;
    float di = g_dinv[i];
    float acc = (sub == 0) ? s0[i] * di * di : 0.f;
    int e0 = g_off[i], e1 = g_off[i + 1];
    for (int j = e0 + sub; j < e1; j += 8) {
        int s = __ldg(&g_csrc[j]);
        acc += s0[s] * g_dinv[s] * di;
    }
#pragma unroll
    for (int o = 4; o; o >>= 1) acc += __shfl_xor_sync(0xffffffffu, acc, o);
    float s1 = acc + bias[0];
    const float4* h4 = (const float4*)(h + (size_t)i * 64);
    float4* d4 = (float4*)(dst + (size_t)i * 64);
#pragma unroll
    for (int t = 0; t < 2; t++) {
        float4 v = h4[sub + t * 8];
        d4[sub + t * 8] = make_float4(s1 * v.x, s1 * v.y, s1 * v.z, s1 * v.w);
    }
}

// ---------------- gate (layer 2) + h3 fused ----------------
__global__ void k_gate2(const float* __restrict__ s0, const float* __restrict__ u,
                        const float* __restrict__ h,
                        const float* __restrict__ bs2, const float* __restrict__ b3,
                        float* __restrict__ dst) {
    int gt = blockIdx.x * blockDim.x + threadIdx.x;
    int i = gt >> 3;
    int sub = threadIdx.x & 7;
    if (i >= NNODE) return;
    float di = g_dinv[i];
    float accS = 0.f, accU = 0.f;
    if (sub == 0) { accS = s0[i] * di * di; accU = u[i] * di * di; }
    int e0 = g_off[i], e1 = g_off[i + 1];
    for (int j = e0 + sub; j < e1; j += 8) {
        int s = __ldg(&g_csrc[j]);
        float w = g_dinv[s] * di;
        accS += s0[s] * w;
        accU += u[s] * w;
    }
#pragma unroll
    for (int o = 4; o; o >>= 1) {
        accS += __shfl_xor_sync(0xffffffffu, accS, o);
        accU += __shfl_xor_sync(0xffffffffu, accU, o);
    }
    float s1 = accS + bs2[0];
    const float4* h4 = (const float4*)(h + (size_t)i * 64);
    float4* d4 = (float4*)(dst + (size_t)i * 64);
#pragma unroll
    for (int t = 0; t < 2; t++) {
        float4 v = h4[sub + t * 8];
        d4[sub + t * 8] = make_float4(s1 * v.x, s1 * v.y, s1 * v.z, s1 * v.w);
    }
    if (sub == 0) g_h3[i] = fmaxf(accU + b3[0], 0.f);
}

// ---------------- fused x3 + sort-pool + conv head ----------------
__global__ void __launch_bounds__(128) k_head(
    const float* __restrict__ Ws3, const float* __restrict__ bs3,
    const float* __restrict__ Wc1, const float* __restrict__ bc1,
    const float* __restrict__ Wc2, const float* __restrict__ bc2,
    const float* __restrict__ Wl1, const float* __restrict__ bl1,
    const float* __restrict__ Wl2, const float* __restrict__ bl2,
    float* __restrict__ out) {
    __shared__ float x3s[NPG];
    __shared__ unsigned long long keys[NPG];
    __shared__ int sel[KSEL];
    __shared__ float pooled[KSEL * DT];
    __shared__ float c1s[16 * 30];
    __shared__ float mps[16 * 15];
    __shared__ float flat[32 * 11];
    __shared__ float red[128];
    int g = blockIdx.x, tid = threadIdx.x;
    int base = g * NPG;

    // x3 for local nodes: s3 aggregation fused in (8 lanes per node)
    {
        float ws3 = Ws3[0], vbs3 = bs3[0];
        int sub = tid & 7;
        int grp = tid >> 3;  // 16 groups
        for (int i = grp; i < NPG; i += 16) {
            int node = base + i;
            float di = g_dinv[node];
            float hi = g_h3[node];
            float acc = (sub == 0) ? hi * di * di : 0.f;
            int e0 = g_off[node], e1 = g_off[node + 1];
            for (int j = e0 + sub; j < e1; j += 8) {
                int s = __ldg(&g_csrc[j]);
                acc += g_h3[s] * g_dinv[s] * di;
            }
#pragma unroll
            for (int o = 4; o; o >>= 1) acc += __shfl_xor_sync(0xffffffffu, acc, o);
            if (sub == 0) x3s[i] = (acc * ws3 + vbs3) * hi;
        }
    }
    __syncthreads();

    // total-order key of (-x3), tie-broken by node index
    for (int i = tid; i < NPG; i += 128) {
        unsigned u = __float_as_uint(-x3s[i]);
        u = (u & 0x80000000u) ? ~u : (u | 0x80000000u);
        keys[i] = ((unsigned long long)u << 32) | (unsigned)i;
    }
    __syncthreads();
    if (tid < NPG) {
        unsigned long long ki = keys[tid];
        int c = 0;
        for (int j = 0; j < NPG; j++) c += (keys[j] < ki) ? 1 : 0;
        if (c < KSEL) sel[c] = tid;
    }
    __syncthreads();
    for (int idx = tid; idx < KSEL * DT; idx += 128) {
        int r = idx / DT, d = idx - r * DT;
        int ln = sel[r];
        float v;
        if (d < 64) v = g_x1[(base + ln) * 64 + d];
        else if (d < 128) v = g_x2[(base + ln) * 64 + d - 64];
        else v = x3s[ln];
        pooled[idx] = v;
    }
    __syncthreads();
    for (int idx = tid; idx < 16 * 30; idx += 128) {
        int o = idx / 30, k = idx - o * 30;
        float acc = bc1[o];
        const float* w = Wc1 + o * DT;
        for (int d = 0; d < DT; d++) acc += pooled[k * DT + d] * w[d];
        c1s[o * 30 + k] = fmaxf(acc, 0.f);
    }
    __syncthreads();
    for (int idx = tid; idx < 16 * 15; idx += 128) {
        int o = idx / 15, p = idx - o * 15;
        mps[idx] = fmaxf(c1s[o * 30 + 2 * p], c1s[o * 30 + 2 * p + 1]);
    }
    __syncthreads();
    for (int idx = tid; idx < 32 * 11; idx += 128) {
        int o = idx / 11, p = idx - o * 11;
        float acc = bc2[o];
        for (int i2 = 0; i2 < 16; i2++) {
            const float* w = Wc2 + (o * 16 + i2) * 5;
#pragma unroll
            for (int t = 0; t < 5; t++) acc += mps[i2 * 15 + p + t] * w[t];
        }
        flat[idx] = fmaxf(acc, 0.f);
    }
    __syncthreads();
    {
        int w = tid >> 5, lane = tid & 31;
        float fl[11];
#pragma unroll
        for (int it = 0; it < 11; it++) fl[it] = flat[lane + it * 32];
        for (int jj = 0; jj < 32; jj++) {
            int j = w * 32 + jj;
            const float* wr = Wl1 + j * 352;
            float acc = 0.f;
#pragma unroll
            for (int it = 0; it < 11; it++) acc += fl[it] * wr[lane + it * 32];
#pragma unroll
            for (int o = 16; o; o >>= 1) acc += __shfl_xor_sync(0xffffffffu, acc, o);
            if (lane == 0) {
                float hv = fmaxf(acc + bl1[j], 0.f);
                red[j] = hv * Wl2[j];
            }
        }
    }
    __syncthreads();
    for (int off = 64; off; off >>= 1) {
        if (tid < off) red[tid] += red[tid + off];
        __syncthreads();
    }
    if (tid == 0) out[g] = red[0] + bl2[0];
}

// ---------------- launcher ----------------
extern "C" void kernel_launch(void* const* d_in, const int* in_sizes, int n_in,
                              void* d_out, int out_size) {
    const float* x   = (const float*)d_in[0];
    const int*   ei  = (const int*)  d_in[1];
    const float* W1  = (const float*)d_in[2];
    const float* b1  = (const float*)d_in[3];
    const float* W2  = (const float*)d_in[4];
    const float* b2  = (const float*)d_in[5];
    const float* W3  = (const float*)d_in[6];
    const float* b3  = (const float*)d_in[7];
    const float* Ws1 = (const float*)d_in[8];
    const float* bs1 = (const float*)d_in[9];
    const float* Ws2 = (const float*)d_in[10];
    const float* bs2 = (const float*)d_in[11];
    const float* Ws3 = (const float*)d_in[12];
    const float* bs3 = (const float*)d_in[13];
    const float* Wc1 = (const float*)d_in[14];
    const float* bc1 = (const float*)d_in[15];
    const float* Wc2 = (const float*)d_in[16];
    const float* bc2 = (const float*)d_in[17];
    const float* Wl1 = (const float*)d_in[18];
    const float* bl1 = (const float*)d_in[19];
    const float* Wl2 = (const float*)d_in[20];
    const float* bl2 = (const float*)d_in[21];
    float* out = (float*)d_out;

    float *dH, *dh, *ds0, *du, *dx1, *dx2;
    cudaGetSymbolAddress((void**)&dH,  g_H);
    cudaGetSymbolAddress((void**)&dh,  g_h);
    cudaGetSymbolAddress((void**)&ds0, g_s0);
    cudaGetSymbolAddress((void**)&du,  g_u);
    cudaGetSymbolAddress((void**)&dx1, g_x1);
    cudaGetSymbolAddress((void**)&dx2, g_x2);

    const int TB = 256;
    int gE  = (EDGES + TB - 1) / TB;
    int gW  = (NNODE * 32 + TB - 1) / TB;
    int gW8 = (NNODE * 8 + TB - 1) / TB;

    // structure
    k_count<<<gE, TB>>>(ei);
    k_scan_dinv<<<1, 1024>>>();
    k_fill<<<gE, TB>>>(ei);

    // layer 1
    k_gemm<FIN><<<(NNODE + 127) / 128, 128>>>(x, W1, dH);
    k_agg64f<<<gW, TB>>>(dH, b1, Ws1, nullptr, dh, ds0, nullptr);
    k_gate<<<gW8, TB>>>(ds0, dh, bs1, dx1);

    // layer 2 (fused dot with W3 for layer 3)
    k_gemm<D><<<(NNODE + 127) / 128, 128>>>(dh, W2, dH);
    k_agg64f<<<gW, TB>>>(dH, b2, Ws2, W3, dh, ds0, du);
    k_gate2<<<gW8, TB>>>(ds0, du, dh, bs2, b3, dx2);

    // fused x3 + head
    k_head<<<NGRAPH, 128>>>(Ws3, bs3, Wc1, bc1, Wc2, bc2, Wl1, bl1, Wl2, bl2, out);

    (void)in_sizes; (void)n_in; (void)out_size;
}

// round 5
// speedup vs baseline: 1.3483x; 1.3483x over previous
#include <cuda_runtime.h>
#include <cuda_bf16.h>

#define NNODE 50000
#define EDGES 600000
#define NGRAPH 500
#define NPG 100
#define KSEL 30
#define FIN 128
#define D 64
#define DT 129
#define SLOT 64

typedef unsigned long long u64;

__device__ __forceinline__ u64 pack2(float lo, float hi) {
    u64 r;
    asm("mov.b64 %0, {%1, %2};" : "=l"(r) : "r"(__float_as_uint(lo)), "r"(__float_as_uint(hi)));
    return r;
}
__device__ __forceinline__ u64 dup2(float v) {
    u64 r;
    asm("mov.b64 %0, {%1, %1};" : "=l"(r) : "r"(__float_as_uint(v)));
    return r;
}
__device__ __forceinline__ void fma2(u64& acc, u64 a, u64 b) {
    asm("fma.rn.f32x2 %0, %1, %2, %0;" : "+l"(acc) : "l"(a), "l"(b));
}

// ---------------- scratch ----------------
__device__ float g_dinv[NNODE];
__device__ int   g_cnt[NNODE];           // zero at call start; k_s3 restores zero
__device__ int   g_slot[NNODE * SLOT];   // bucketed adjacency (sources per dst)
__device__ float g_H[NNODE * D];
__device__ float g_h[NNODE * D];
__device__ float g_s0[NNODE];
__device__ float g_u[NNODE];
__device__ float g_h3[NNODE];
__device__ float g_x1[NNODE * D];
__device__ float g_x2[NNODE * D];
__device__ float g_x3[NNODE];

// ---------------- setup: bucket fill + dinv ----------------
__global__ void k_fillslots(const int* __restrict__ ei) {
    int e = blockIdx.x * blockDim.x + threadIdx.x;
    if (e >= EDGES) return;
    int s = ei[e];
    int d = ei[EDGES + e];
    int p = atomicAdd(&g_cnt[d], 1);
    g_slot[d * SLOT + p] = s;
}

__global__ void k_dinv() {
    int i = blockIdx.x * blockDim.x + threadIdx.x;
    if (i >= NNODE) return;
    g_dinv[i] = rsqrtf((float)g_cnt[i] + 1.0f);
}

// ---------------- SGEMM (f32x2): out[N,64] = X[N,K] @ W[K,64] ----------------
// 256 threads, BM=128, BN=64, BK=16, thread tile 4x8
template <int K>
__global__ void __launch_bounds__(256) k_gemm(const float* __restrict__ X,
                                              const float* __restrict__ W,
                                              float* __restrict__ out) {
    __shared__ float Xt[16][132];
    __shared__ float Wsm[16][64];
    int tid = threadIdx.x;
    int rb = blockIdx.x * 128;
    int tx = tid & 7;        // col group (8 cols)
    int ty = tid >> 3;       // row group (4 rows), 0..31
    u64 acc2[4][4];
#pragma unroll
    for (int r = 0; r < 4; r++)
#pragma unroll
        for (int c = 0; c < 4; c++) acc2[r][c] = 0ULL;
#pragma unroll 1
    for (int k0 = 0; k0 < K; k0 += 16) {
#pragma unroll
        for (int i = 0; i < 2; i++) {
            int f = tid + i * 256;          // 0..511
            int row = f >> 2;
            int kk4 = f & 3;
            float4 v = make_float4(0.f, 0.f, 0.f, 0.f);
            int gr = rb + row;
            if (gr < NNODE) v = *(const float4*)(X + (size_t)gr * K + k0 + kk4 * 4);
            Xt[kk4 * 4 + 0][row] = v.x;
            Xt[kk4 * 4 + 1][row] = v.y;
            Xt[kk4 * 4 + 2][row] = v.z;
            Xt[kk4 * 4 + 3][row] = v.w;
        }
        {
            int kk = tid >> 4, c4 = tid & 15;
            *(float4*)&Wsm[kk][c4 * 4] = *(const float4*)(W + (size_t)(k0 + kk) * 64 + c4 * 4);
        }
        __syncthreads();
#pragma unroll
        for (int kk = 0; kk < 16; kk++) {
            float a[4];
            *(float4*)&a[0] = *(const float4*)&Xt[kk][ty * 4];
            u64 b2[4];
            const u64* bp = (const u64*)&Wsm[kk][tx * 8];
            b2[0] = bp[0]; b2[1] = bp[1]; b2[2] = bp[2]; b2[3] = bp[3];
#pragma unroll
            for (int r = 0; r < 4; r++) {
                u64 ar = dup2(a[r]);
#pragma unroll
                for (int c = 0; c < 4; c++) fma2(acc2[r][c], ar, b2[c]);
            }
        }
        __syncthreads();
    }
#pragma unroll
    for (int r = 0; r < 4; r++) {
        int gr = rb + ty * 4 + r;
        if (gr < NNODE) {
            float2 p0 = *(float2*)&acc2[r][0];
            float2 p1 = *(float2*)&acc2[r][1];
            float2 p2 = *(float2*)&acc2[r][2];
            float2 p3 = *(float2*)&acc2[r][3];
            float4* op = (float4*)(out + (size_t)gr * 64 + tx * 8);
            op[0] = make_float4(p0.x, p0.y, p1.x, p1.y);
            op[1] = make_float4(p2.x, p2.y, p3.x, p3.y);
        }
    }
}

// ---------------- 64-wide GCN aggregation + fused dots (f32x2) ----------------
__global__ void k_agg64f(const float* __restrict__ Hin, const float* __restrict__ bias,
                         const float* __restrict__ Wg, const float* __restrict__ Wu,
                         float* __restrict__ out, float* __restrict__ sg,
                         float* __restrict__ su) {
    int warp = (blockIdx.x * blockDim.x + threadIdx.x) >> 5;
    int lane = threadIdx.x & 31;
    if (warp >= NNODE) return;
    int i = warp;
    float di = g_dinv[i];
    float di2 = di * di;
    const u64* Hu = (const u64*)Hin;
    float2 self = ((const float2*)Hin)[i * 32 + lane];
    float2 bv = ((const float2*)bias)[lane];
    u64 acc = pack2(fmaf(self.x, di2, bv.x), fmaf(self.y, di2, bv.y));
    const int* sl = g_slot + (size_t)i * SLOT;
    int deg = g_cnt[i];
    int j = 0;
    for (; j + 4 <= deg; j += 4) {
        int s0 = __ldg(&sl[j]);
        int s1 = __ldg(&sl[j + 1]);
        int s2 = __ldg(&sl[j + 2]);
        int s3 = __ldg(&sl[j + 3]);
        u64 v0 = __ldg(&Hu[s0 * 32 + lane]);
        u64 v1 = __ldg(&Hu[s1 * 32 + lane]);
        u64 v2 = __ldg(&Hu[s2 * 32 + lane]);
        u64 v3 = __ldg(&Hu[s3 * 32 + lane]);
        fma2(acc, v0, dup2(g_dinv[s0] * di));
        fma2(acc, v1, dup2(g_dinv[s1] * di));
        fma2(acc, v2, dup2(g_dinv[s2] * di));
        fma2(acc, v3, dup2(g_dinv[s3] * di));
    }
    for (; j < deg; j++) {
        int s = __ldg(&sl[j]);
        u64 v = __ldg(&Hu[s * 32 + lane]);
        fma2(acc, v, dup2(g_dinv[s] * di));
    }
    float2 av = *(float2*)&acc;
    float ax = fmaxf(av.x, 0.f);
    float ay = fmaxf(av.y, 0.f);
    ((float2*)out)[i * 32 + lane] = make_float2(ax, ay);
    float2 wg = ((const float2*)Wg)[lane];
    float dg = ax * wg.x + ay * wg.y;
#pragma unroll
    for (int o = 16; o; o >>= 1) dg += __shfl_xor_sync(0xffffffffu, dg, o);
    if (lane == 0) sg[i] = dg;
    if (Wu) {
        float2 wu = ((const float2*)Wu)[lane];
        float du = ax * wu.x + ay * wu.y;
#pragma unroll
        for (int o = 16; o; o >>= 1) du += __shfl_xor_sync(0xffffffffu, du, o);
        if (lane == 0) su[i] = du;
    }
}

// ---------------- gate (layer 1): 8 lanes per node ----------------
__global__ void k_gate(const float* __restrict__ s0, const float* __restrict__ h,
                       const float* __restrict__ bias, float* __restrict__ dst) {
    int gt = blockIdx.x * blockDim.x + threadIdx.x;
    int i = gt >> 3;
    int sub = threadIdx.x & 7;
    if (i >= NNODE) return;
    float di = g_dinv[i];
    float acc = (sub == 0) ? s0[i] * di * di : 0.f;
    const int* sl = g_slot + (size_t)i * SLOT;
    int deg = g_cnt[i];
    for (int j = sub; j < deg; j += 8) {
        int s = __ldg(&sl[j]);
        acc += s0[s] * g_dinv[s] * di;
    }
#pragma unroll
    for (int o = 4; o; o >>= 1) acc += __shfl_xor_sync(0xffffffffu, acc, o);
    float s1 = acc + bias[0];
    const float4* h4 = (const float4*)(h + (size_t)i * 64);
    float4* d4 = (float4*)(dst + (size_t)i * 64);
#pragma unroll
    for (int t = 0; t < 2; t++) {
        float4 v = h4[sub + t * 8];
        d4[sub + t * 8] = make_float4(s1 * v.x, s1 * v.y, s1 * v.z, s1 * v.w);
    }
}

// ---------------- gate (layer 2) + h3 fused ----------------
__global__ void k_gate2(const float* __restrict__ s0, const float* __restrict__ u,
                        const float* __restrict__ h,
                        const float* __restrict__ bs2, const float* __restrict__ b3,
                        float* __restrict__ dst) {
    int gt = blockIdx.x * blockDim.x + threadIdx.x;
    int i = gt >> 3;
    int sub = threadIdx.x & 7;
    if (i >= NNODE) return;
    float di = g_dinv[i];
    float accS = 0.f, accU = 0.f;
    if (sub == 0) { accS = s0[i] * di * di; accU = u[i] * di * di; }
    const int* sl = g_slot + (size_t)i * SLOT;
    int deg = g_cnt[i];
    for (int j = sub; j < deg; j += 8) {
        int s = __ldg(&sl[j]);
        float w = g_dinv[s] * di;
        accS += s0[s] * w;
        accU += u[s] * w;
    }
#pragma unroll
    for (int o = 4; o; o >>= 1) {
        accS += __shfl_xor_sync(0xffffffffu, accS, o);
        accU += __shfl_xor_sync(0xffffffffu, accU, o);
    }
    float s1 = accS + bs2[0];
    const float4* h4 = (const float4*)(h + (size_t)i * 64);
    float4* d4 = (float4*)(dst + (size_t)i * 64);
#pragma unroll
    for (int t = 0; t < 2; t++) {
        float4 v = h4[sub + t * 8];
        d4[sub + t * 8] = make_float4(s1 * v.x, s1 * v.y, s1 * v.z, s1 * v.w);
    }
    if (sub == 0) g_h3[i] = fmaxf(accU + b3[0], 0.f);
}

// ---------------- s3/x3 (8 lanes per node); restores g_cnt=0 for next call ----------------
__global__ void k_s3(const float* __restrict__ Ws3, const float* __restrict__ bs3) {
    int gt = blockIdx.x * blockDim.x + threadIdx.x;
    int i = gt >> 3;
    int sub = threadIdx.x & 7;
    if (i >= NNODE) return;
    float di = g_dinv[i];
    float hi = g_h3[i];
    float acc = (sub == 0) ? hi * di * di : 0.f;
    const int* sl = g_slot + (size_t)i * SLOT;
    int deg = g_cnt[i];
    for (int j = sub; j < deg; j += 8) {
        int s = __ldg(&sl[j]);
        acc += g_h3[s] * g_dinv[s] * di;
    }
#pragma unroll
    for (int o = 4; o; o >>= 1) acc += __shfl_xor_sync(0xffffffffu, acc, o);
    if (sub == 0) {
        g_x3[i] = (acc * Ws3[0] + bs3[0]) * hi;
        g_cnt[i] = 0;   // restore invariant for next kernel_launch call
    }
}

// ---------------- fused sort-pool + conv head ----------------
__global__ void __launch_bounds__(128) k_head(
    const float* __restrict__ Wc1, const float* __restrict__ bc1,
    const float* __restrict__ Wc2, const float* __restrict__ bc2,
    const float* __restrict__ Wl1, const float* __restrict__ bl1,
    const float* __restrict__ Wl2, const float* __restrict__ bl2,
    float* __restrict__ out) {
    __shared__ float x3s[NPG];
    __shared__ unsigned long long keys[NPG];
    __shared__ int sel[KSEL];
    __shared__ float pooled[KSEL * DT];
    __shared__ float c1s[16 * 30];
    __shared__ float mps[16 * 15];
    __shared__ float flat[32 * 11];
    __shared__ float red[128];
    int g = blockIdx.x, tid = threadIdx.x;
    int base = g * NPG;

    for (int i = tid; i < NPG; i += 128) x3s[i] = g_x3[base + i];
    __syncthreads();
    for (int i = tid; i < NPG; i += 128) {
        unsigned u = __float_as_uint(-x3s[i]);
        u = (u & 0x80000000u) ? ~u : (u | 0x80000000u);
        keys[i] = ((unsigned long long)u << 32) | (unsigned)i;
    }
    __syncthreads();
    if (tid < NPG) {
        unsigned long long ki = keys[tid];
        int c = 0;
        for (int j = 0; j < NPG; j++) c += (keys[j] < ki) ? 1 : 0;
        if (c < KSEL) sel[c] = tid;
    }
    __syncthreads();
    for (int idx = tid; idx < KSEL * DT; idx += 128) {
        int r = idx / DT, d = idx - r * DT;
        int ln = sel[r];
        float v;
        if (d < 64) v = g_x1[(base + ln) * 64 + d];
        else if (d < 128) v = g_x2[(base + ln) * 64 + d - 64];
        else v = x3s[ln];
        pooled[idx] = v;
    }
    __syncthreads();
    for (int idx = tid; idx < 16 * 30; idx += 128) {
        int o = idx / 30, k = idx - o * 30;
        float acc = bc1[o];
        const float* w = Wc1 + o * DT;
        for (int d = 0; d < DT; d++) acc += pooled[k * DT + d] * w[d];
        c1s[o * 30 + k] = fmaxf(acc, 0.f);
    }
    __syncthreads();
    for (int idx = tid; idx < 16 * 15; idx += 128) {
        int o = idx / 15, p = idx - o * 15;
        mps[idx] = fmaxf(c1s[o * 30 + 2 * p], c1s[o * 30 + 2 * p + 1]);
    }
    __syncthreads();
    for (int idx = tid; idx < 32 * 11; idx += 128) {
        int o = idx / 11, p = idx - o * 11;
        float acc = bc2[o];
        for (int i2 = 0; i2 < 16; i2++) {
            const float* w = Wc2 + (o * 16 + i2) * 5;
#pragma unroll
            for (int t = 0; t < 5; t++) acc += mps[i2 * 15 + p + t] * w[t];
        }
        flat[idx] = fmaxf(acc, 0.f);
    }
    __syncthreads();
    {
        int w = tid >> 5, lane = tid & 31;
        float fl[11];
#pragma unroll
        for (int it = 0; it < 11; it++) fl[it] = flat[lane + it * 32];
        for (int jj = 0; jj < 32; jj++) {
            int j = w * 32 + jj;
            const float* wr = Wl1 + j * 352;
            float acc = 0.f;
#pragma unroll
            for (int it = 0; it < 11; it++) acc += fl[it] * wr[lane + it * 32];
#pragma unroll
            for (int o = 16; o; o >>= 1) acc += __shfl_xor_sync(0xffffffffu, acc, o);
            if (lane == 0) {
                float hv = fmaxf(acc + bl1[j], 0.f);
                red[j] = hv * Wl2[j];
            }
        }
    }
    __syncthreads();
    for (int off = 64; off; off >>= 1) {
        if (tid < off) red[tid] += red[tid + off];
        __syncthreads();
    }
    if (tid == 0) out[g] = red[0] + bl2[0];
}

// ---------------- launcher ----------------
extern "C" void kernel_launch(void* const* d_in, const int* in_sizes, int n_in,
                              void* d_out, int out_size) {
    const float* x   = (const float*)d_in[0];
    const int*   ei  = (const int*)  d_in[1];
    const float* W1  = (const float*)d_in[2];
    const float* b1  = (const float*)d_in[3];
    const float* W2  = (const float*)d_in[4];
    const float* b2  = (const float*)d_in[5];
    const float* W3  = (const float*)d_in[6];
    const float* b3  = (const float*)d_in[7];
    const float* Ws1 = (const float*)d_in[8];
    const float* bs1 = (const float*)d_in[9];
    const float* Ws2 = (const float*)d_in[10];
    const float* bs2 = (const float*)d_in[11];
    const float* Ws3 = (const float*)d_in[12];
    const float* bs3 = (const float*)d_in[13];
    const float* Wc1 = (const float*)d_in[14];
    const float* bc1 = (const float*)d_in[15];
    const float* Wc2 = (const float*)d_in[16];
    const float* bc2 = (const float*)d_in[17];
    const float* Wl1 = (const float*)d_in[18];
    const float* bl1 = (const float*)d_in[19];
    const float* Wl2 = (const float*)d_in[20];
    const float* bl2 = (const float*)d_in[21];
    float* out = (float*)d_out;

    float *dH, *dh, *ds0, *du, *dx1, *dx2;
    cudaGetSymbolAddress((void**)&dH,  g_H);
    cudaGetSymbolAddress((void**)&dh,  g_h);
    cudaGetSymbolAddress((void**)&ds0, g_s0);
    cudaGetSymbolAddress((void**)&du,  g_u);
    cudaGetSymbolAddress((void**)&dx1, g_x1);
    cudaGetSymbolAddress((void**)&dx2, g_x2);

    const int TB = 256;
    int gE  = (EDGES + TB - 1) / TB;
    int gN  = (NNODE + TB - 1) / TB;
    int gW  = (NNODE * 32 + TB - 1) / TB;
    int gW8 = (NNODE * 8 + TB - 1) / TB;

    // 0: gemm128 (independent of graph structure)
    k_gemm<FIN><<<(NNODE + 127) / 128, 256>>>(x, W1, dH);
    // 1-2: structure
    k_fillslots<<<gE, TB>>>(ei);
    k_dinv<<<gN, TB>>>();
    // 3: agg64f #1  <-- profiled slot
    k_agg64f<<<gW, TB>>>(dH, b1, Ws1, nullptr, dh, ds0, nullptr);
    // 4: gate1
    k_gate<<<gW8, TB>>>(ds0, dh, bs1, dx1);
    // 5: gemm64
    k_gemm<D><<<(NNODE + 127) / 128, 256>>>(dh, W2, dH);
    // 6: agg64f #2 (fused dot with W3)
    k_agg64f<<<gW, TB>>>(dH, b2, Ws2, W3, dh, ds0, du);
    // 7: gate2 + h3
    k_gate2<<<gW8, TB>>>(ds0, du, dh, bs2, b3, dx2);
    // 8: s3/x3 (+ cnt reset)
    k_s3<<<gW8, TB>>>(Ws3, bs3);
    // 9: head
    k_head<<<NGRAPH, 128>>>(Wc1, bc1, Wc2, bc2, Wl1, bl1, Wl2, bl2, out);

    (void)in_sizes; (void)n_in; (void)out_size;
}

// round 6
// speedup vs baseline: 1.4592x; 1.0823x over previous
#include <cuda_runtime.h>
#include <cuda_bf16.h>

#define NNODE 50000
#define EDGES 600000
#define NGRAPH 500
#define NPG 100
#define KSEL 30
#define FIN 128
#define D 64
#define DT 129
#define SLOT 64

typedef unsigned long long u64;

__device__ __forceinline__ u64 pack2(float lo, float hi) {
    u64 r;
    asm("mov.b64 %0, {%1, %2};" : "=l"(r) : "r"(__float_as_uint(lo)), "r"(__float_as_uint(hi)));
    return r;
}
__device__ __forceinline__ u64 dup2(float v) {
    u64 r;
    asm("mov.b64 %0, {%1, %1};" : "=l"(r) : "r"(__float_as_uint(v)));
    return r;
}
__device__ __forceinline__ void fma2(u64& acc, u64 a, u64 b) {
    asm("fma.rn.f32x2 %0, %1, %2, %0;" : "+l"(acc) : "l"(a), "l"(b));
}
__device__ __forceinline__ void add2(u64& acc, u64 v) {
    asm("add.rn.f32x2 %0, %1, %0;" : "+l"(acc) : "l"(v));
}

// ---------------- scratch ----------------
__device__ float g_dinv[NNODE];
__device__ int   g_cnt[NNODE];           // zero at call start; k_s3 restores zero
__device__ int   g_slot[NNODE * SLOT];
__device__ float g_H[NNODE * D];         // pre-scaled (row * dinv[row])
__device__ float g_h[NNODE * D];         // post-agg activations (unscaled)
__device__ float g_s0[NNODE];            // pre-scaled gate dots
__device__ float g_u[NNODE];             // pre-scaled layer-3 dots
__device__ float g_h3[NNODE];            // h3 (unscaled)
__device__ float g_h3s[NNODE];           // h3 * dinv
__device__ float g_x1[NNODE * D];
__device__ float g_x2[NNODE * D];
__device__ float g_x3[NNODE];

// ---------------- setup ----------------
__global__ void k_fillslots(const int* __restrict__ ei) {
    int e = blockIdx.x * blockDim.x + threadIdx.x;
    if (e >= EDGES) return;
    int s = ei[e];
    int d = ei[EDGES + e];
    int p = atomicAdd(&g_cnt[d], 1);
    g_slot[d * SLOT + p] = s;
}

__global__ void k_dinv() {
    int i = blockIdx.x * blockDim.x + threadIdx.x;
    if (i >= NNODE) return;
    g_dinv[i] = rsqrtf((float)g_cnt[i] + 1.0f);
}

// ---------------- SGEMM (f32x2) with dinv-scaled epilogue ----------------
// out[r,:] = (X[r,:] @ W) * dinv[r]
template <int K>
__global__ void __launch_bounds__(256) k_gemm(const float* __restrict__ X,
                                              const float* __restrict__ W,
                                              float* __restrict__ out) {
    __shared__ float Xt[16][132];
    __shared__ float Wsm[16][64];
    int tid = threadIdx.x;
    int rb = blockIdx.x * 128;
    int tx = tid & 7;
    int ty = tid >> 3;
    u64 acc2[4][4];
#pragma unroll
    for (int r = 0; r < 4; r++)
#pragma unroll
        for (int c = 0; c < 4; c++) acc2[r][c] = 0ULL;
#pragma unroll 1
    for (int k0 = 0; k0 < K; k0 += 16) {
#pragma unroll
        for (int i = 0; i < 2; i++) {
            int f = tid + i * 256;
            int row = f >> 2;
            int kk4 = f & 3;
            float4 v = make_float4(0.f, 0.f, 0.f, 0.f);
            int gr = rb + row;
            if (gr < NNODE) v = *(const float4*)(X + (size_t)gr * K + k0 + kk4 * 4);
            Xt[kk4 * 4 + 0][row] = v.x;
            Xt[kk4 * 4 + 1][row] = v.y;
            Xt[kk4 * 4 + 2][row] = v.z;
            Xt[kk4 * 4 + 3][row] = v.w;
        }
        {
            int kk = tid >> 4, c4 = tid & 15;
            *(float4*)&Wsm[kk][c4 * 4] = *(const float4*)(W + (size_t)(k0 + kk) * 64 + c4 * 4);
        }
        __syncthreads();
#pragma unroll
        for (int kk = 0; kk < 16; kk++) {
            float a[4];
            *(float4*)&a[0] = *(const float4*)&Xt[kk][ty * 4];
            u64 b2[4];
            const u64* bp = (const u64*)&Wsm[kk][tx * 8];
            b2[0] = bp[0]; b2[1] = bp[1]; b2[2] = bp[2]; b2[3] = bp[3];
#pragma unroll
            for (int r = 0; r < 4; r++) {
                u64 ar = dup2(a[r]);
#pragma unroll
                for (int c = 0; c < 4; c++) fma2(acc2[r][c], ar, b2[c]);
            }
        }
        __syncthreads();
    }
#pragma unroll
    for (int r = 0; r < 4; r++) {
        int gr = rb + ty * 4 + r;
        if (gr < NNODE) {
            float sc = g_dinv[gr];
            float2 p0 = *(float2*)&acc2[r][0];
            float2 p1 = *(float2*)&acc2[r][1];
            float2 p2 = *(float2*)&acc2[r][2];
            float2 p3 = *(float2*)&acc2[r][3];
            float4* op = (float4*)(out + (size_t)gr * 64 + tx * 8);
            op[0] = make_float4(p0.x * sc, p0.y * sc, p1.x * sc, p1.y * sc);
            op[1] = make_float4(p2.x * sc, p2.y * sc, p3.x * sc, p3.y * sc);
        }
    }
}

// ---------------- 64-wide aggregation (pre-scaled input) + fused dots ----------------
// out = relu( di * (Hin[i] + Σ_s Hin[s]) + bias )
// sg[i] = dot(out, Wg) * di ; su[i] = dot(out, Wu) * di (pre-scaled for next agg)
__global__ void k_agg64f(const float* __restrict__ Hin, const float* __restrict__ bias,
                         const float* __restrict__ Wg, const float* __restrict__ Wu,
                         float* __restrict__ out, float* __restrict__ sg,
                         float* __restrict__ su) {
    int warp = (blockIdx.x * blockDim.x + threadIdx.x) >> 5;
    int lane = threadIdx.x & 31;
    if (warp >= NNODE) return;
    int i = warp;
    float di = g_dinv[i];
    const u64* Hu = (const u64*)Hin;
    u64 acc = __ldg(&Hu[i * 32 + lane]);
    const int* sl = g_slot + (size_t)i * SLOT;
    int deg = g_cnt[i];
    int j = 0;
    for (; j + 4 <= deg; j += 4) {
        int s0 = __ldg(&sl[j]);
        int s1 = __ldg(&sl[j + 1]);
        int s2 = __ldg(&sl[j + 2]);
        int s3 = __ldg(&sl[j + 3]);
        u64 v0 = __ldg(&Hu[s0 * 32 + lane]);
        u64 v1 = __ldg(&Hu[s1 * 32 + lane]);
        u64 v2 = __ldg(&Hu[s2 * 32 + lane]);
        u64 v3 = __ldg(&Hu[s3 * 32 + lane]);
        add2(acc, v0);
        add2(acc, v1);
        add2(acc, v2);
        add2(acc, v3);
    }
    for (; j < deg; j++) {
        int s = __ldg(&sl[j]);
        u64 v = __ldg(&Hu[s * 32 + lane]);
        add2(acc, v);
    }
    float2 av = *(float2*)&acc;
    float2 bv = ((const float2*)bias)[lane];
    float ax = fmaxf(fmaf(av.x, di, bv.x), 0.f);
    float ay = fmaxf(fmaf(av.y, di, bv.y), 0.f);
    ((float2*)out)[i * 32 + lane] = make_float2(ax, ay);
    float2 wg = ((const float2*)Wg)[lane];
    float dg = ax * wg.x + ay * wg.y;
#pragma unroll
    for (int o = 16; o; o >>= 1) dg += __shfl_xor_sync(0xffffffffu, dg, o);
    if (lane == 0) sg[i] = dg * di;
    if (Wu) {
        float2 wu = ((const float2*)Wu)[lane];
        float du = ax * wu.x + ay * wu.y;
#pragma unroll
        for (int o = 16; o; o >>= 1) du += __shfl_xor_sync(0xffffffffu, du, o);
        if (lane == 0) su[i] = du * di;
    }
}

// ---------------- gate (layer 1): 8 lanes per node ; s0 is pre-scaled ----------------
__global__ void k_gate(const float* __restrict__ s0, const float* __restrict__ h,
                       const float* __restrict__ bias, float* __restrict__ dst) {
    int gt = blockIdx.x * blockDim.x + threadIdx.x;
    int i = gt >> 3;
    int sub = threadIdx.x & 7;
    if (i >= NNODE) return;
    float di = g_dinv[i];
    float acc = (sub == 0) ? s0[i] : 0.f;
    const int* sl = g_slot + (size_t)i * SLOT;
    int deg = g_cnt[i];
    for (int j = sub; j < deg; j += 8) {
        int s = __ldg(&sl[j]);
        acc += s0[s];
    }
#pragma unroll
    for (int o = 4; o; o >>= 1) acc += __shfl_xor_sync(0xffffffffu, acc, o);
    float s1 = fmaf(acc, di, bias[0]);
    const float4* h4 = (const float4*)(h + (size_t)i * 64);
    float4* d4 = (float4*)(dst + (size_t)i * 64);
#pragma unroll
    for (int t = 0; t < 2; t++) {
        float4 v = h4[sub + t * 8];
        d4[sub + t * 8] = make_float4(s1 * v.x, s1 * v.y, s1 * v.z, s1 * v.w);
    }
}

// ---------------- gate (layer 2) + h3 fused ; s0,u pre-scaled ----------------
__global__ void k_gate2(const float* __restrict__ s0, const float* __restrict__ u,
                        const float* __restrict__ h,
                        const float* __restrict__ bs2, const float* __restrict__ b3,
                        float* __restrict__ dst) {
    int gt = blockIdx.x * blockDim.x + threadIdx.x;
    int i = gt >> 3;
    int sub = threadIdx.x & 7;
    if (i >= NNODE) return;
    float di = g_dinv[i];
    float accS = 0.f, accU = 0.f;
    if (sub == 0) { accS = s0[i]; accU = u[i]; }
    const int* sl = g_slot + (size_t)i * SLOT;
    int deg = g_cnt[i];
    for (int j = sub; j < deg; j += 8) {
        int s = __ldg(&sl[j]);
        accS += s0[s];
        accU += u[s];
    }
#pragma unroll
    for (int o = 4; o; o >>= 1) {
        accS += __shfl_xor_sync(0xffffffffu, accS, o);
        accU += __shfl_xor_sync(0xffffffffu, accU, o);
    }
    float s1 = fmaf(accS, di, bs2[0]);
    const float4* h4 = (const float4*)(h + (size_t)i * 64);
    float4* d4 = (float4*)(dst + (size_t)i * 64);
#pragma unroll
    for (int t = 0; t < 2; t++) {
        float4 v = h4[sub + t * 8];
        d4[sub + t * 8] = make_float4(s1 * v.x, s1 * v.y, s1 * v.z, s1 * v.w);
    }
    if (sub == 0) {
        float h3 = fmaxf(fmaf(accU, di, b3[0]), 0.f);
        g_h3[i] = h3;
        g_h3s[i] = h3 * di;
    }
}

// ---------------- s3/x3 ; restores g_cnt=0 ----------------
__global__ void k_s3(const float* __restrict__ Ws3, const float* __restrict__ bs3) {
    int gt = blockIdx.x * blockDim.x + threadIdx.x;
    int i = gt >> 3;
    int sub = threadIdx.x & 7;
    if (i >= NNODE) return;
    float di = g_dinv[i];
    float acc = (sub == 0) ? g_h3s[i] : 0.f;
    const int* sl = g_slot + (size_t)i * SLOT;
    int deg = g_cnt[i];
    for (int j = sub; j < deg; j += 8) {
        int s = __ldg(&sl[j]);
        acc += g_h3s[s];
    }
#pragma unroll
    for (int o = 4; o; o >>= 1) acc += __shfl_xor_sync(0xffffffffu, acc, o);
    if (sub == 0) {
        g_x3[i] = fmaf(acc * di, Ws3[0], bs3[0]) * g_h3[i];
        g_cnt[i] = 0;   // restore invariant for next call
    }
}

// ---------------- fused sort-pool + conv head ----------------
__global__ void __launch_bounds__(128) k_head(
    const float* __restrict__ Wc1, const float* __restrict__ bc1,
    const float* __restrict__ Wc2, const float* __restrict__ bc2,
    const float* __restrict__ Wl1, const float* __restrict__ bl1,
    const float* __restrict__ Wl2, const float* __restrict__ bl2,
    float* __restrict__ out) {
    __shared__ float x3s[NPG];
    __shared__ unsigned long long keys[NPG];
    __shared__ int sel[KSEL];
    __shared__ float pooled[KSEL * DT];
    __shared__ float c1s[16 * 30];
    __shared__ float mps[16 * 15];
    __shared__ float flat[32 * 11];
    __shared__ float red[128];
    int g = blockIdx.x, tid = threadIdx.x;
    int base = g * NPG;

    for (int i = tid; i < NPG; i += 128) x3s[i] = g_x3[base + i];
    __syncthreads();
    for (int i = tid; i < NPG; i += 128) {
        unsigned u = __float_as_uint(-x3s[i]);
        u = (u & 0x80000000u) ? ~u : (u | 0x80000000u);
        keys[i] = ((unsigned long long)u << 32) | (unsigned)i;
    }
    __syncthreads();
    if (tid < NPG) {
        unsigned long long ki = keys[tid];
        int c = 0;
        for (int j = 0; j < NPG; j++) c += (keys[j] < ki) ? 1 : 0;
        if (c < KSEL) sel[c] = tid;
    }
    __syncthreads();
    for (int idx = tid; idx < KSEL * DT; idx += 128) {
        int r = idx / DT, d = idx - r * DT;
        int ln = sel[r];
        float v;
        if (d < 64) v = g_x1[(base + ln) * 64 + d];
        else if (d < 128) v = g_x2[(base + ln) * 64 + d - 64];
        else v = x3s[ln];
        pooled[idx] = v;
    }
    __syncthreads();
    for (int idx = tid; idx < 16 * 30; idx += 128) {
        int o = idx / 30, k = idx - o * 30;
        float acc = bc1[o];
        const float* w = Wc1 + o * DT;
        for (int d = 0; d < DT; d++) acc += pooled[k * DT + d] * w[d];
        c1s[o * 30 + k] = fmaxf(acc, 0.f);
    }
    __syncthreads();
    for (int idx = tid; idx < 16 * 15; idx += 128) {
        int o = idx / 15, p = idx - o * 15;
        mps[idx] = fmaxf(c1s[o * 30 + 2 * p], c1s[o * 30 + 2 * p + 1]);
    }
    __syncthreads();
    for (int idx = tid; idx < 32 * 11; idx += 128) {
        int o = idx / 11, p = idx - o * 11;
        float acc = bc2[o];
        for (int i2 = 0; i2 < 16; i2++) {
            const float* w = Wc2 + (o * 16 + i2) * 5;
#pragma unroll
            for (int t = 0; t < 5; t++) acc += mps[i2 * 15 + p + t] * w[t];
        }
        flat[idx] = fmaxf(acc, 0.f);
    }
    __syncthreads();
    {
        int w = tid >> 5, lane = tid & 31;
        float fl[11];
#pragma unroll
        for (int it = 0; it < 11; it++) fl[it] = flat[lane + it * 32];
        for (int jj = 0; jj < 32; jj++) {
            int j = w * 32 + jj;
            const float* wr = Wl1 + j * 352;
            float acc = 0.f;
#pragma unroll
            for (int it = 0; it < 11; it++) acc += fl[it] * wr[lane + it * 32];
#pragma unroll
            for (int o = 16; o; o >>= 1) acc += __shfl_xor_sync(0xffffffffu, acc, o);
            if (lane == 0) {
                float hv = fmaxf(acc + bl1[j], 0.f);
                red[j] = hv * Wl2[j];
            }
        }
    }
    __syncthreads();
    for (int off = 64; off; off >>= 1) {
        if (tid < off) red[tid] += red[tid + off];
        __syncthreads();
    }
    if (tid == 0) out[g] = red[0] + bl2[0];
}

// ---------------- launcher ----------------
extern "C" void kernel_launch(void* const* d_in, const int* in_sizes, int n_in,
                              void* d_out, int out_size) {
    const float* x   = (const float*)d_in[0];
    const int*   ei  = (const int*)  d_in[1];
    const float* W1  = (const float*)d_in[2];
    const float* b1  = (const float*)d_in[3];
    const float* W2  = (const float*)d_in[4];
    const float* b2  = (const float*)d_in[5];
    const float* W3  = (const float*)d_in[6];
    const float* b3  = (const float*)d_in[7];
    const float* Ws1 = (const float*)d_in[8];
    const float* bs1 = (const float*)d_in[9];
    const float* Ws2 = (const float*)d_in[10];
    const float* bs2 = (const float*)d_in[11];
    const float* Ws3 = (const float*)d_in[12];
    const float* bs3 = (const float*)d_in[13];
    const float* Wc1 = (const float*)d_in[14];
    const float* bc1 = (const float*)d_in[15];
    const float* Wc2 = (const float*)d_in[16];
    const float* bc2 = (const float*)d_in[17];
    const float* Wl1 = (const float*)d_in[18];
    const float* bl1 = (const float*)d_in[19];
    const float* Wl2 = (const float*)d_in[20];
    const float* bl2 = (const float*)d_in[21];
    float* out = (float*)d_out;

    float *dH, *dh, *ds0, *du, *dx1, *dx2;
    cudaGetSymbolAddress((void**)&dH,  g_H);
    cudaGetSymbolAddress((void**)&dh,  g_h);
    cudaGetSymbolAddress((void**)&ds0, g_s0);
    cudaGetSymbolAddress((void**)&du,  g_u);
    cudaGetSymbolAddress((void**)&dx1, g_x1);
    cudaGetSymbolAddress((void**)&dx2, g_x2);

    const int TB = 256;
    int gE  = (EDGES + TB - 1) / TB;
    int gN  = (NNODE + TB - 1) / TB;
    int gW  = (NNODE * 32 + TB - 1) / TB;
    int gW8 = (NNODE * 8 + TB - 1) / TB;

    // 0-1: structure (dinv needed by gemm epilogue)
    k_fillslots<<<gE, TB>>>(ei);
    k_dinv<<<gN, TB>>>();
    // 2: gemm128 (scaled epilogue)
    k_gemm<FIN><<<(NNODE + 127) / 128, 256>>>(x, W1, dH);
    // 3: agg64f #1  <-- profiled slot
    k_agg64f<<<gW, TB>>>(dH, b1, Ws1, nullptr, dh, ds0, nullptr);
    // 4: gate1
    k_gate<<<gW8, TB>>>(ds0, dh, bs1, dx1);
    // 5: gemm64 (scaled epilogue)
    k_gemm<D><<<(NNODE + 127) / 128, 256>>>(dh, W2, dH);
    // 6: agg64f #2 (fused dots for gate2 and layer 3)
    k_agg64f<<<gW, TB>>>(dH, b2, Ws2, W3, dh, ds0, du);
    // 7: gate2 + h3
    k_gate2<<<gW8, TB>>>(ds0, du, dh, bs2, b3, dx2);
    // 8: s3/x3 (+ cnt reset)
    k_s3<<<gW8, TB>>>(Ws3, bs3);
    // 9: head
    k_head<<<NGRAPH, 128>>>(Wc1, bc1, Wc2, bc2, Wl1, bl1, Wl2, bl2, out);

    (void)in_sizes; (void)n_in; (void)out_size;
}

// round 7
// speedup vs baseline: 1.4628x; 1.0025x over previous
#include <cuda_runtime.h>
#include <cuda_bf16.h>

#define NNODE 50000
#define EDGES 600000
#define NGRAPH 500
#define NPG 100
#define KSEL 30
#define FIN 128
#define D 64
#define DT 129
#define SLOT 64

typedef unsigned long long u64;

__device__ __forceinline__ u64 dup2(float v) {
    u64 r;
    asm("mov.b64 %0, {%1, %1};" : "=l"(r) : "r"(__float_as_uint(v)));
    return r;
}
__device__ __forceinline__ void fma2(u64& acc, u64 a, u64 b) {
    asm("fma.rn.f32x2 %0, %1, %2, %0;" : "+l"(acc) : "l"(a), "l"(b));
}
__device__ __forceinline__ void add2(u64& acc, u64 v) {
    asm("add.rn.f32x2 %0, %1, %0;" : "+l"(acc) : "l"(v));
}

// ---------------- scratch ----------------
__device__ float g_dinv[NNODE];
__device__ int   g_cnt[NNODE];           // zero at call start; k_s3 restores zero
__device__ int   g_slot[NNODE * SLOT];
__device__ float g_H[NNODE * D];         // pre-scaled (row * dinv[row])
__device__ float g_h[NNODE * D];
__device__ float g_s0[NNODE];
__device__ float g_u[NNODE];
__device__ float g_h3[NNODE];
__device__ float g_h3s[NNODE];
__device__ float g_x1[NNODE * D];
__device__ float g_x2[NNODE * D];
__device__ float g_x3[NNODE];

// ---------------- setup ----------------
__global__ void k_fillslots(const int* __restrict__ ei) {
    int e = blockIdx.x * blockDim.x + threadIdx.x;
    if (e >= EDGES) return;
    int s = ei[e];
    int d = ei[EDGES + e];
    int p = atomicAdd(&g_cnt[d], 1);
    g_slot[d * SLOT + p] = s;
}

__global__ void k_dinv() {
    int i = blockIdx.x * blockDim.x + threadIdx.x;
    if (i >= NNODE) return;
    g_dinv[i] = rsqrtf((float)g_cnt[i] + 1.0f);
}

// ---------------- SGEMM (f32x2, register double-buffered) ----------------
// out[r,:] = (X[r,:] @ W) * dinv[r]
template <int K>
__global__ void __launch_bounds__(256) k_gemm(const float* __restrict__ X,
                                              const float* __restrict__ W,
                                              float* __restrict__ out) {
    __shared__ float Xt[16][132];
    __shared__ float Wsm[16][64];
    int tid = threadIdx.x;
    int rb = blockIdx.x * 128;
    int tx = tid & 7;
    int ty = tid >> 3;
    // X load mapping: thread handles 2 float4s
    int fr0 = tid >> 2;            // row for first
    int fk0 = tid & 3;             // k-quad for first
    int fr1 = (tid + 256) >> 2;
    int fk1 = (tid + 256) & 3;
    int wkk = tid >> 4, wc4 = tid & 15;

    u64 acc2[4][4];
#pragma unroll
    for (int r = 0; r < 4; r++)
#pragma unroll
        for (int c = 0; c < 4; c++) acc2[r][c] = 0ULL;

    float4 xA, xB, wv;
    {
        int grA = rb + fr0, grB = rb + fr1;
        xA = (grA < NNODE) ? *(const float4*)(X + (size_t)grA * K + fk0 * 4)
                           : make_float4(0.f, 0.f, 0.f, 0.f);
        xB = (grB < NNODE) ? *(const float4*)(X + (size_t)grB * K + fk1 * 4)
                           : make_float4(0.f, 0.f, 0.f, 0.f);
        wv = *(const float4*)(W + (size_t)wkk * 64 + wc4 * 4);
    }
#pragma unroll 1
    for (int k0 = 0; k0 < K; k0 += 16) {
        // store current tile to smem
        Xt[fk0 * 4 + 0][fr0] = xA.x; Xt[fk0 * 4 + 1][fr0] = xA.y;
        Xt[fk0 * 4 + 2][fr0] = xA.z; Xt[fk0 * 4 + 3][fr0] = xA.w;
        Xt[fk1 * 4 + 0][fr1] = xB.x; Xt[fk1 * 4 + 1][fr1] = xB.y;
        Xt[fk1 * 4 + 2][fr1] = xB.z; Xt[fk1 * 4 + 3][fr1] = xB.w;
        *(float4*)&Wsm[wkk][wc4 * 4] = wv;
        __syncthreads();
        // prefetch next tile
        if (k0 + 16 < K) {
            int grA = rb + fr0, grB = rb + fr1;
            xA = (grA < NNODE) ? *(const float4*)(X + (size_t)grA * K + k0 + 16 + fk0 * 4)
                               : make_float4(0.f, 0.f, 0.f, 0.f);
            xB = (grB < NNODE) ? *(const float4*)(X + (size_t)grB * K + k0 + 16 + fk1 * 4)
                               : make_float4(0.f, 0.f, 0.f, 0.f);
            wv = *(const float4*)(W + (size_t)(k0 + 16 + wkk) * 64 + wc4 * 4);
        }
#pragma unroll
        for (int kk = 0; kk < 16; kk++) {
            float a[4];
            *(float4*)&a[0] = *(const float4*)&Xt[kk][ty * 4];
            u64 b2[4];
            const u64* bp = (const u64*)&Wsm[kk][tx * 8];
            b2[0] = bp[0]; b2[1] = bp[1]; b2[2] = bp[2]; b2[3] = bp[3];
#pragma unroll
            for (int r = 0; r < 4; r++) {
                u64 ar = dup2(a[r]);
#pragma unroll
                for (int c = 0; c < 4; c++) fma2(acc2[r][c], ar, b2[c]);
            }
        }
        __syncthreads();
    }
#pragma unroll
    for (int r = 0; r < 4; r++) {
        int gr = rb + ty * 4 + r;
        if (gr < NNODE) {
            float sc = g_dinv[gr];
            float2 p0 = *(float2*)&acc2[r][0];
            float2 p1 = *(float2*)&acc2[r][1];
            float2 p2 = *(float2*)&acc2[r][2];
            float2 p3 = *(float2*)&acc2[r][3];
            float4* op = (float4*)(out + (size_t)gr * 64 + tx * 8);
            op[0] = make_float4(p0.x * sc, p0.y * sc, p1.x * sc, p1.y * sc);
            op[1] = make_float4(p2.x * sc, p2.y * sc, p3.x * sc, p3.y * sc);
        }
    }
}

// ---------------- 64-wide aggregation: half-warp float4 gathers ----------------
// out = relu( di*(Hin[i] + Σ_s Hin[s]) + bias ), Hin pre-scaled by dinv[row]
// sg = dot(out,Wg)*di ; su = dot(out,Wu)*di
__global__ void k_agg64f(const float* __restrict__ Hin, const float* __restrict__ bias,
                         const float* __restrict__ Wg, const float* __restrict__ Wu,
                         float* __restrict__ out, float* __restrict__ sg,
                         float* __restrict__ su) {
    int warp = (blockIdx.x * blockDim.x + threadIdx.x) >> 5;
    int lane = threadIdx.x & 31;
    if (warp >= NNODE) return;
    int i = warp;
    int half = lane >> 4;
    int l16 = lane & 15;
    const float4* H4 = (const float4*)Hin;
    u64 accL = 0ULL, accH = 0ULL;   // channels (4*l16, 4*l16+1), (4*l16+2, 4*l16+3)
    if (half == 0) {
        float4 v = __ldg(&H4[i * 16 + l16]);
        accL = *(u64*)&v.x;
        accH = *(u64*)&v.z;
    }
    const int* sl = g_slot + (size_t)i * SLOT;
    int deg = g_cnt[i];
    int j = 0;
    for (; j + 4 <= deg; j += 4) {
        int4 ss = __ldg((const int4*)(sl + j));
        int sA = half ? ss.y : ss.x;
        int sB = half ? ss.w : ss.z;
        float4 vA = __ldg(&H4[sA * 16 + l16]);
        float4 vB = __ldg(&H4[sB * 16 + l16]);
        add2(accL, *(u64*)&vA.x);
        add2(accH, *(u64*)&vA.z);
        add2(accL, *(u64*)&vB.x);
        add2(accH, *(u64*)&vB.z);
    }
    if (j + 2 <= deg) {
        int2 ss = __ldg((const int2*)(sl + j));
        int s = half ? ss.y : ss.x;
        float4 v = __ldg(&H4[s * 16 + l16]);
        add2(accL, *(u64*)&v.x);
        add2(accH, *(u64*)&v.z);
        j += 2;
    }
    if (j < deg && half == 0) {
        int s = __ldg(&sl[j]);
        float4 v = __ldg(&H4[s * 16 + l16]);
        add2(accL, *(u64*)&v.x);
        add2(accH, *(u64*)&v.z);
    }
    // combine halves (xor 16): every lane ends with the full per-channel sums
    float2 aL = *(float2*)&accL;
    float2 aH = *(float2*)&accH;
    aL.x += __shfl_xor_sync(0xffffffffu, aL.x, 16);
    aL.y += __shfl_xor_sync(0xffffffffu, aL.y, 16);
    aH.x += __shfl_xor_sync(0xffffffffu, aH.x, 16);
    aH.y += __shfl_xor_sync(0xffffffffu, aH.y, 16);
    float di = g_dinv[i];
    float4 bv = __ldg(&((const float4*)bias)[l16]);
    float r0 = fmaxf(fmaf(aL.x, di, bv.x), 0.f);
    float r1 = fmaxf(fmaf(aL.y, di, bv.y), 0.f);
    float r2 = fmaxf(fmaf(aH.x, di, bv.z), 0.f);
    float r3 = fmaxf(fmaf(aH.y, di, bv.w), 0.f);
    if (half == 0)
        ((float4*)out)[i * 16 + l16] = make_float4(r0, r1, r2, r3);
    // dots: per-lane dot4, reduce across 16 lanes (both halves hold same values)
    float4 wg = __ldg(&((const float4*)Wg)[l16]);
    float dg = r0 * wg.x + r1 * wg.y + r2 * wg.z + r3 * wg.w;
#pragma unroll
    for (int o = 8; o; o >>= 1) dg += __shfl_xor_sync(0xffffffffu, dg, o);
    if (lane == 0) sg[i] = dg * di;
    if (Wu) {
        float4 wu = __ldg(&((const float4*)Wu)[l16]);
        float du = r0 * wu.x + r1 * wu.y + r2 * wu.z + r3 * wu.w;
#pragma unroll
        for (int o = 8; o; o >>= 1) du += __shfl_xor_sync(0xffffffffu, du, o);
        if (lane == 0) su[i] = du * di;
    }
}

// ---------------- gate (layer 1): 8 lanes per node ; s0 pre-scaled ----------------
__global__ void k_gate(const float* __restrict__ s0, const float* __restrict__ h,
                       const float* __restrict__ bias, float* __restrict__ dst) {
    int gt = blockIdx.x * blockDim.x + threadIdx.x;
    int i = gt >> 3;
    int sub = threadIdx.x & 7;
    if (i >= NNODE) return;
    float di = g_dinv[i];
    float acc = (sub == 0) ? s0[i] : 0.f;
    const int* sl = g_slot + (size_t)i * SLOT;
    int deg = g_cnt[i];
    for (int j = sub; j < deg; j += 8) {
        int s = __ldg(&sl[j]);
        acc += s0[s];
    }
#pragma unroll
    for (int o = 4; o; o >>= 1) acc += __shfl_xor_sync(0xffffffffu, acc, o);
    float s1 = fmaf(acc, di, bias[0]);
    const float4* h4 = (const float4*)(h + (size_t)i * 64);
    float4* d4 = (float4*)(dst + (size_t)i * 64);
#pragma unroll
    for (int t = 0; t < 2; t++) {
        float4 v = h4[sub + t * 8];
        d4[sub + t * 8] = make_float4(s1 * v.x, s1 * v.y, s1 * v.z, s1 * v.w);
    }
}

// ---------------- gate (layer 2) + h3 fused ----------------
__global__ void k_gate2(const float* __restrict__ s0, const float* __restrict__ u,
                        const float* __restrict__ h,
                        const float* __restrict__ bs2, const float* __restrict__ b3,
                        float* __restrict__ dst) {
    int gt = blockIdx.x * blockDim.x + threadIdx.x;
    int i = gt >> 3;
    int sub = threadIdx.x & 7;
    if (i >= NNODE) return;
    float di = g_dinv[i];
    float accS = 0.f, accU = 0.f;
    if (sub == 0) { accS = s0[i]; accU = u[i]; }
    const int* sl = g_slot + (size_t)i * SLOT;
    int deg = g_cnt[i];
    for (int j = sub; j < deg; j += 8) {
        int s = __ldg(&sl[j]);
        accS += s0[s];
        accU += u[s];
    }
#pragma unroll
    for (int o = 4; o; o >>= 1) {
        accS += __shfl_xor_sync(0xffffffffu, accS, o);
        accU += __shfl_xor_sync(0xffffffffu, accU, o);
    }
    float s1 = fmaf(accS, di, bs2[0]);
    const float4* h4 = (const float4*)(h + (size_t)i * 64);
    float4* d4 = (float4*)(dst + (size_t)i * 64);
#pragma unroll
    for (int t = 0; t < 2; t++) {
        float4 v = h4[sub + t * 8];
        d4[sub + t * 8] = make_float4(s1 * v.x, s1 * v.y, s1 * v.z, s1 * v.w);
    }
    if (sub == 0) {
        float h3 = fmaxf(fmaf(accU, di, b3[0]), 0.f);
        g_h3[i] = h3;
        g_h3s[i] = h3 * di;
    }
}

// ---------------- s3/x3 ; restores g_cnt=0 ----------------
__global__ void k_s3(const float* __restrict__ Ws3, const float* __restrict__ bs3) {
    int gt = blockIdx.x * blockDim.x + threadIdx.x;
    int i = gt >> 3;
    int sub = threadIdx.x & 7;
    if (i >= NNODE) return;
    float di = g_dinv[i];
    float acc = (sub == 0) ? g_h3s[i] : 0.f;
    const int* sl = g_slot + (size_t)i * SLOT;
    int deg = g_cnt[i];
    for (int j = sub; j < deg; j += 8) {
        int s = __ldg(&sl[j]);
        acc += g_h3s[s];
    }
#pragma unroll
    for (int o = 4; o; o >>= 1) acc += __shfl_xor_sync(0xffffffffu, acc, o);
    if (sub == 0) {
        g_x3[i] = fmaf(acc * di, Ws3[0], bs3[0]) * g_h3[i];
        g_cnt[i] = 0;
    }
}

// ---------------- fused sort-pool + conv head ----------------
__global__ void __launch_bounds__(128) k_head(
    const float* __restrict__ Wc1, const float* __restrict__ bc1,
    const float* __restrict__ Wc2, const float* __restrict__ bc2,
    const float* __restrict__ Wl1, const float* __restrict__ bl1,
    const float* __restrict__ Wl2, const float* __restrict__ bl2,
    float* __restrict__ out) {
    __shared__ float x3s[NPG];
    __shared__ unsigned long long keys[NPG];
    __shared__ int sel[KSEL];
    __shared__ float pooled[KSEL * DT];
    __shared__ float c1s[16 * 30];
    __shared__ float mps[16 * 15];
    __shared__ float flat[32 * 11];
    __shared__ float red[128];
    int g = blockIdx.x, tid = threadIdx.x;
    int base = g * NPG;

    for (int i = tid; i < NPG; i += 128) x3s[i] = g_x3[base + i];
    __syncthreads();
    for (int i = tid; i < NPG; i += 128) {
        unsigned u = __float_as_uint(-x3s[i]);
        u = (u & 0x80000000u) ? ~u : (u | 0x80000000u);
        keys[i] = ((unsigned long long)u << 32) | (unsigned)i;
    }
    __syncthreads();
    if (tid < NPG) {
        unsigned long long ki = keys[tid];
        int c = 0;
        for (int j = 0; j < NPG; j++) c += (keys[j] < ki) ? 1 : 0;
        if (c < KSEL) sel[c] = tid;
    }
    __syncthreads();
    for (int idx = tid; idx < KSEL * DT; idx += 128) {
        int r = idx / DT, d = idx - r * DT;
        int ln = sel[r];
        float v;
        if (d < 64) v = g_x1[(base + ln) * 64 + d];
        else if (d < 128) v = g_x2[(base + ln) * 64 + d - 64];
        else v = x3s[ln];
        pooled[idx] = v;
    }
    __syncthreads();
    for (int idx = tid; idx < 16 * 30; idx += 128) {
        int o = idx / 30, k = idx - o * 30;
        float acc = bc1[o];
        const float* w = Wc1 + o * DT;
        for (int d = 0; d < DT; d++) acc += pooled[k * DT + d] * w[d];
        c1s[o * 30 + k] = fmaxf(acc, 0.f);
    }
    __syncthreads();
    for (int idx = tid; idx < 16 * 15; idx += 128) {
        int o = idx / 15, p = idx - o * 15;
        mps[idx] = fmaxf(c1s[o * 30 + 2 * p], c1s[o * 30 + 2 * p + 1]);
    }
    __syncthreads();
    for (int idx = tid; idx < 32 * 11; idx += 128) {
        int o = idx / 11, p = idx - o * 11;
        float acc = bc2[o];
        for (int i2 = 0; i2 < 16; i2++) {
            const float* w = Wc2 + (o * 16 + i2) * 5;
#pragma unroll
            for (int t = 0; t < 5; t++) acc += mps[i2 * 15 + p + t] * w[t];
        }
        flat[idx] = fmaxf(acc, 0.f);
    }
    __syncthreads();
    {
        int w = tid >> 5, lane = tid & 31;
        float fl[11];
#pragma unroll
        for (int it = 0; it < 11; it++) fl[it] = flat[lane + it * 32];
        for (int jj = 0; jj < 32; jj++) {
            int j = w * 32 + jj;
            const float* wr = Wl1 + j * 352;
            float acc = 0.f;
#pragma unroll
            for (int it = 0; it < 11; it++) acc += fl[it] * wr[lane + it * 32];
#pragma unroll
            for (int o = 16; o; o >>= 1) acc += __shfl_xor_sync(0xffffffffu, acc, o);
            if (lane == 0) {
                float hv = fmaxf(acc + bl1[j], 0.f);
                red[j] = hv * Wl2[j];
            }
        }
    }
    __syncthreads();
    for (int off = 64; off; off >>= 1) {
        if (tid < off) red[tid] += red[tid + off];
        __syncthreads();
    }
    if (tid == 0) out[g] = red[0] + bl2[0];
}

// ---------------- launcher ----------------
extern "C" void kernel_launch(void* const* d_in, const int* in_sizes, int n_in,
                              void* d_out, int out_size) {
    const float* x   = (const float*)d_in[0];
    const int*   ei  = (const int*)  d_in[1];
    const float* W1  = (const float*)d_in[2];
    const float* b1  = (const float*)d_in[3];
    const float* W2  = (const float*)d_in[4];
    const float* b2  = (const float*)d_in[5];
    const float* W3  = (const float*)d_in[6];
    const float* b3  = (const float*)d_in[7];
    const float* Ws1 = (const float*)d_in[8];
    const float* bs1 = (const float*)d_in[9];
    const float* Ws2 = (const float*)d_in[10];
    const float* bs2 = (const float*)d_in[11];
    const float* Ws3 = (const float*)d_in[12];
    const float* bs3 = (const float*)d_in[13];
    const float* Wc1 = (const float*)d_in[14];
    const float* bc1 = (const float*)d_in[15];
    const float* Wc2 = (const float*)d_in[16];
    const float* bc2 = (const float*)d_in[17];
    const float* Wl1 = (const float*)d_in[18];
    const float* bl1 = (const float*)d_in[19];
    const float* Wl2 = (const float*)d_in[20];
    const float* bl2 = (const float*)d_in[21];
    float* out = (float*)d_out;

    float *dH, *dh, *ds0, *du, *dx1, *dx2;
    cudaGetSymbolAddress((void**)&dH,  g_H);
    cudaGetSymbolAddress((void**)&dh,  g_h);
    cudaGetSymbolAddress((void**)&ds0, g_s0);
    cudaGetSymbolAddress((void**)&du,  g_u);
    cudaGetSymbolAddress((void**)&dx1, g_x1);
    cudaGetSymbolAddress((void**)&dx2, g_x2);

    const int TB = 256;
    int gE  = (EDGES + TB - 1) / TB;
    int gN  = (NNODE + TB - 1) / TB;
    int gW  = (NNODE * 32 + TB - 1) / TB;
    int gW8 = (NNODE * 8 + TB - 1) / TB;

    // 0-1: structure
    k_fillslots<<<gE, TB>>>(ei);
    k_dinv<<<gN, TB>>>();
    // 2: gemm128
    k_gemm<FIN><<<(NNODE + 127) / 128, 256>>>(x, W1, dH);
    // 3: agg64f #1  <-- profiled slot
    k_agg64f<<<gW, TB>>>(dH, b1, Ws1, nullptr, dh, ds0, nullptr);
    // 4: gate1
    k_gate<<<gW8, TB>>>(ds0, dh, bs1, dx1);
    // 5: gemm64
    k_gemm<D><<<(NNODE + 127) / 128, 256>>>(dh, W2, dH);
    // 6: agg64f #2
    k_agg64f<<<gW, TB>>>(dH, b2, Ws2, W3, dh, ds0, du);
    // 7: gate2 + h3
    k_gate2<<<gW8, TB>>>(ds0, du, dh, bs2, b3, dx2);
    // 8: s3/x3 (+ cnt reset)
    k_s3<<<gW8, TB>>>(Ws3, bs3);
    // 9: head
    k_head<<<NGRAPH, 128>>>(Wc1, bc1, Wc2, bc2, Wl1, bl1, Wl2, bl2, out);

    (void)in_sizes; (void)n_in; (void)out_size;
}

// round 8
// speedup vs baseline: 1.5052x; 1.0290x over previous
#include <cuda_runtime.h>
#include <cuda_bf16.h>

#define NNODE 50000
#define EDGES 600000
#define NGRAPH 500
#define NPG 100
#define KSEL 30
#define FIN 128
#define D 64
#define DT 129
#define SLOT 64

typedef unsigned long long u64;

__device__ __forceinline__ u64 dup2(float v) {
    u64 r;
    asm("mov.b64 %0, {%1, %1};" : "=l"(r) : "r"(__float_as_uint(v)));
    return r;
}
__device__ __forceinline__ void fma2(u64& acc, u64 a, u64 b) {
    asm("fma.rn.f32x2 %0, %1, %2, %0;" : "+l"(acc) : "l"(a), "l"(b));
}
__device__ __forceinline__ void add2(u64& acc, u64 v) {
    asm("add.rn.f32x2 %0, %1, %0;" : "+l"(acc) : "l"(v));
}

// ---------------- scratch ----------------
__device__ int   g_cnt[NNODE];           // zero at call start; k_s3 restores zero
__device__ int   g_slot[NNODE * SLOT];
__device__ float g_H[NNODE * D];         // pre-scaled (row * dinv[row])
__device__ float g_h[NNODE * D];
__device__ float g_s0[NNODE];
__device__ float g_u[NNODE];
__device__ float g_h3[NNODE];
__device__ float g_h3s[NNODE];
__device__ float g_x1[NNODE * D];
__device__ float g_x2[NNODE * D];
__device__ float g_x3[NNODE];

// ---------------- setup ----------------
__global__ void k_fillslots(const int* __restrict__ ei) {
    int e = blockIdx.x * blockDim.x + threadIdx.x;
    if (e >= EDGES) return;
    int s = ei[e];
    int d = ei[EDGES + e];
    int p = atomicAdd(&g_cnt[d], 1);
    g_slot[d * SLOT + p] = s;
}

// ---------------- SGEMM (f32x2, register double-buffered) ----------------
// out[r,:] = (X[r,:] @ W) * rsqrt(cnt[r]+1)
template <int K>
__global__ void __launch_bounds__(256) k_gemm(const float* __restrict__ X,
                                              const float* __restrict__ W,
                                              float* __restrict__ out) {
    __shared__ float Xt[16][132];
    __shared__ float Wsm[16][64];
    int tid = threadIdx.x;
    int rb = blockIdx.x * 128;
    int tx = tid & 7;
    int ty = tid >> 3;
    int fr0 = tid >> 2;
    int fk0 = tid & 3;
    int fr1 = (tid + 256) >> 2;
    int fk1 = (tid + 256) & 3;
    int wkk = tid >> 4, wc4 = tid & 15;

    u64 acc2[4][4];
#pragma unroll
    for (int r = 0; r < 4; r++)
#pragma unroll
        for (int c = 0; c < 4; c++) acc2[r][c] = 0ULL;

    float4 xA, xB, wv;
    {
        int grA = rb + fr0, grB = rb + fr1;
        xA = (grA < NNODE) ? *(const float4*)(X + (size_t)grA * K + fk0 * 4)
                           : make_float4(0.f, 0.f, 0.f, 0.f);
        xB = (grB < NNODE) ? *(const float4*)(X + (size_t)grB * K + fk1 * 4)
                           : make_float4(0.f, 0.f, 0.f, 0.f);
        wv = *(const float4*)(W + (size_t)wkk * 64 + wc4 * 4);
    }
#pragma unroll 1
    for (int k0 = 0; k0 < K; k0 += 16) {
        Xt[fk0 * 4 + 0][fr0] = xA.x; Xt[fk0 * 4 + 1][fr0] = xA.y;
        Xt[fk0 * 4 + 2][fr0] = xA.z; Xt[fk0 * 4 + 3][fr0] = xA.w;
        Xt[fk1 * 4 + 0][fr1] = xB.x; Xt[fk1 * 4 + 1][fr1] = xB.y;
        Xt[fk1 * 4 + 2][fr1] = xB.z; Xt[fk1 * 4 + 3][fr1] = xB.w;
        *(float4*)&Wsm[wkk][wc4 * 4] = wv;
        __syncthreads();
        if (k0 + 16 < K) {
            int grA = rb + fr0, grB = rb + fr1;
            xA = (grA < NNODE) ? *(const float4*)(X + (size_t)grA * K + k0 + 16 + fk0 * 4)
                               : make_float4(0.f, 0.f, 0.f, 0.f);
            xB = (grB < NNODE) ? *(const float4*)(X + (size_t)grB * K + k0 + 16 + fk1 * 4)
                               : make_float4(0.f, 0.f, 0.f, 0.f);
            wv = *(const float4*)(W + (size_t)(k0 + 16 + wkk) * 64 + wc4 * 4);
        }
#pragma unroll
        for (int kk = 0; kk < 16; kk++) {
            float a[4];
            *(float4*)&a[0] = *(const float4*)&Xt[kk][ty * 4];
            u64 b2[4];
            const u64* bp = (const u64*)&Wsm[kk][tx * 8];
            b2[0] = bp[0]; b2[1] = bp[1]; b2[2] = bp[2]; b2[3] = bp[3];
#pragma unroll
            for (int r = 0; r < 4; r++) {
                u64 ar = dup2(a[r]);
#pragma unroll
                for (int c = 0; c < 4; c++) fma2(acc2[r][c], ar, b2[c]);
            }
        }
        __syncthreads();
    }
#pragma unroll
    for (int r = 0; r < 4; r++) {
        int gr = rb + ty * 4 + r;
        if (gr < NNODE) {
            float sc = rsqrtf((float)g_cnt[gr] + 1.0f);
            float2 p0 = *(float2*)&acc2[r][0];
            float2 p1 = *(float2*)&acc2[r][1];
            float2 p2 = *(float2*)&acc2[r][2];
            float2 p3 = *(float2*)&acc2[r][3];
            float4* op = (float4*)(out + (size_t)gr * 64 + tx * 8);
            op[0] = make_float4(p0.x * sc, p0.y * sc, p1.x * sc, p1.y * sc);
            op[1] = make_float4(p2.x * sc, p2.y * sc, p3.x * sc, p3.y * sc);
        }
    }
}

// ---------------- 64-wide aggregation (full-warp float2) + fused dots ----------------
// out = relu( di*(Hin[i] + Σ_s Hin[s]) + bias ), Hin pre-scaled
// sg = dot(out,Wg)*di ; su = dot(out,Wu)*di
__global__ void k_agg64f(const float* __restrict__ Hin, const float* __restrict__ bias,
                         const float* __restrict__ Wg, const float* __restrict__ Wu,
                         float* __restrict__ out, float* __restrict__ sg,
                         float* __restrict__ su) {
    int warp = (blockIdx.x * blockDim.x + threadIdx.x) >> 5;
    int lane = threadIdx.x & 31;
    if (warp >= NNODE) return;
    int i = warp;
    int cnt = g_cnt[i];
    float di = rsqrtf((float)cnt + 1.0f);
    const u64* Hu = (const u64*)Hin;
    u64 acc = __ldg(&Hu[i * 32 + lane]);
    const int* sl = g_slot + (size_t)i * SLOT;
    int j = 0;
    for (; j + 4 <= cnt; j += 4) {
        int4 ss = __ldg((const int4*)(sl + j));
        u64 v0 = __ldg(&Hu[ss.x * 32 + lane]);
        u64 v1 = __ldg(&Hu[ss.y * 32 + lane]);
        u64 v2 = __ldg(&Hu[ss.z * 32 + lane]);
        u64 v3 = __ldg(&Hu[ss.w * 32 + lane]);
        add2(acc, v0);
        add2(acc, v1);
        add2(acc, v2);
        add2(acc, v3);
    }
    for (; j < cnt; j++) {
        int s = __ldg(&sl[j]);
        u64 v = __ldg(&Hu[s * 32 + lane]);
        add2(acc, v);
    }
    float2 av = *(float2*)&acc;
    float2 bv = ((const float2*)bias)[lane];
    float ax = fmaxf(fmaf(av.x, di, bv.x), 0.f);
    float ay = fmaxf(fmaf(av.y, di, bv.y), 0.f);
    ((float2*)out)[i * 32 + lane] = make_float2(ax, ay);
    float2 wg = ((const float2*)Wg)[lane];
    float dg = ax * wg.x + ay * wg.y;
#pragma unroll
    for (int o = 16; o; o >>= 1) dg += __shfl_xor_sync(0xffffffffu, dg, o);
    if (lane == 0) sg[i] = dg * di;
    if (Wu) {
        float2 wu = ((const float2*)Wu)[lane];
        float du = ax * wu.x + ay * wu.y;
#pragma unroll
        for (int o = 16; o; o >>= 1) du += __shfl_xor_sync(0xffffffffu, du, o);
        if (lane == 0) su[i] = du * di;
    }
}

// ---------------- gate (layer 1): 8 lanes per node ; s0 pre-scaled ----------------
__global__ void k_gate(const float* __restrict__ s0, const float* __restrict__ h,
                       const float* __restrict__ bias, float* __restrict__ dst) {
    int gt = blockIdx.x * blockDim.x + threadIdx.x;
    int i = gt >> 3;
    int sub = threadIdx.x & 7;
    if (i >= NNODE) return;
    int cnt = g_cnt[i];
    float di = rsqrtf((float)cnt + 1.0f);
    float acc = (sub == 0) ? s0[i] : 0.f;
    const int* sl = g_slot + (size_t)i * SLOT;
    for (int j = sub; j < cnt; j += 8) {
        int s = __ldg(&sl[j]);
        acc += s0[s];
    }
#pragma unroll
    for (int o = 4; o; o >>= 1) acc += __shfl_xor_sync(0xffffffffu, acc, o);
    float s1 = fmaf(acc, di, bias[0]);
    const float4* h4 = (const float4*)(h + (size_t)i * 64);
    float4* d4 = (float4*)(dst + (size_t)i * 64);
#pragma unroll
    for (int t = 0; t < 2; t++) {
        float4 v = h4[sub + t * 8];
        d4[sub + t * 8] = make_float4(s1 * v.x, s1 * v.y, s1 * v.z, s1 * v.w);
    }
}

// ---------------- gate (layer 2) + h3 fused ----------------
__global__ void k_gate2(const float* __restrict__ s0, const float* __restrict__ u,
                        const float* __restrict__ h,
                        const float* __restrict__ bs2, const float* __restrict__ b3,
                        float* __restrict__ dst) {
    int gt = blockIdx.x * blockDim.x + threadIdx.x;
    int i = gt >> 3;
    int sub = threadIdx.x & 7;
    if (i >= NNODE) return;
    int cnt = g_cnt[i];
    float di = rsqrtf((float)cnt + 1.0f);
    float accS = 0.f, accU = 0.f;
    if (sub == 0) { accS = s0[i]; accU = u[i]; }
    const int* sl = g_slot + (size_t)i * SLOT;
    for (int j = sub; j < cnt; j += 8) {
        int s = __ldg(&sl[j]);
        accS += s0[s];
        accU += u[s];
    }
#pragma unroll
    for (int o = 4; o; o >>= 1) {
        accS += __shfl_xor_sync(0xffffffffu, accS, o);
        accU += __shfl_xor_sync(0xffffffffu, accU, o);
    }
    float s1 = fmaf(accS, di, bs2[0]);
    const float4* h4 = (const float4*)(h + (size_t)i * 64);
    float4* d4 = (float4*)(dst + (size_t)i * 64);
#pragma unroll
    for (int t = 0; t < 2; t++) {
        float4 v = h4[sub + t * 8];
        d4[sub + t * 8] = make_float4(s1 * v.x, s1 * v.y, s1 * v.z, s1 * v.w);
    }
    if (sub == 0) {
        float h3 = fmaxf(fmaf(accU, di, b3[0]), 0.f);
        g_h3[i] = h3;
        g_h3s[i] = h3 * di;
    }
}

// ---------------- s3/x3 ; restores g_cnt=0 ----------------
__global__ void k_s3(const float* __restrict__ Ws3, const float* __restrict__ bs3) {
    int gt = blockIdx.x * blockDim.x + threadIdx.x;
    int i = gt >> 3;
    int sub = threadIdx.x & 7;
    if (i >= NNODE) return;
    int cnt = g_cnt[i];
    float di = rsqrtf((float)cnt + 1.0f);
    float acc = (sub == 0) ? g_h3s[i] : 0.f;
    const int* sl = g_slot + (size_t)i * SLOT;
    for (int j = sub; j < cnt; j += 8) {
        int s = __ldg(&sl[j]);
        acc += g_h3s[s];
    }
#pragma unroll
    for (int o = 4; o; o >>= 1) acc += __shfl_xor_sync(0xffffffffu, acc, o);
    if (sub == 0) {
        g_x3[i] = fmaf(acc * di, Ws3[0], bs3[0]) * g_h3[i];
        g_cnt[i] = 0;
    }
}

// ---------------- fused sort-pool + conv head ----------------
__global__ void __launch_bounds__(128) k_head(
    const float* __restrict__ Wc1, const float* __restrict__ bc1,
    const float* __restrict__ Wc2, const float* __restrict__ bc2,
    const float* __restrict__ Wl1, const float* __restrict__ bl1,
    const float* __restrict__ Wl2, const float* __restrict__ bl2,
    float* __restrict__ out) {
    __shared__ float x3s[NPG];
    __shared__ unsigned long long keys[NPG];
    __shared__ int sel[KSEL];
    __shared__ float pooled[KSEL * DT];
    __shared__ float c1s[16 * 30];
    __shared__ float mps[16 * 15];
    __shared__ float flat[32 * 11];
    __shared__ float red[128];
    int g = blockIdx.x, tid = threadIdx.x;
    int base = g * NPG;

    for (int i = tid; i < NPG; i += 128) x3s[i] = g_x3[base + i];
    __syncthreads();
    for (int i = tid; i < NPG; i += 128) {
        unsigned u = __float_as_uint(-x3s[i]);
        u = (u & 0x80000000u) ? ~u : (u | 0x80000000u);
        keys[i] = ((unsigned long long)u << 32) | (unsigned)i;
    }
    __syncthreads();
    if (tid < NPG) {
        unsigned long long ki = keys[tid];
        int c = 0;
        for (int j = 0; j < NPG; j++) c += (keys[j] < ki) ? 1 : 0;
        if (c < KSEL) sel[c] = tid;
    }
    __syncthreads();
    for (int idx = tid; idx < KSEL * DT; idx += 128) {
        int r = idx / DT, d = idx - r * DT;
        int ln = sel[r];
        float v;
        if (d < 64) v = g_x1[(base + ln) * 64 + d];
        else if (d < 128) v = g_x2[(base + ln) * 64 + d - 64];
        else v = x3s[ln];
        pooled[idx] = v;
    }
    __syncthreads();
    for (int idx = tid; idx < 16 * 30; idx += 128) {
        int o = idx / 30, k = idx - o * 30;
        float acc = bc1[o];
        const float* w = Wc1 + o * DT;
        for (int d = 0; d < DT; d++) acc += pooled[k * DT + d] * w[d];
        c1s[o * 30 + k] = fmaxf(acc, 0.f);
    }
    __syncthreads();
    for (int idx = tid; idx < 16 * 15; idx += 128) {
        int o = idx / 15, p = idx - o * 15;
        mps[idx] = fmaxf(c1s[o * 30 + 2 * p], c1s[o * 30 + 2 * p + 1]);
    }
    __syncthreads();
    for (int idx = tid; idx < 32 * 11; idx += 128) {
        int o = idx / 11, p = idx - o * 11;
        float acc = bc2[o];
        for (int i2 = 0; i2 < 16; i2++) {
            const float* w = Wc2 + (o * 16 + i2) * 5;
#pragma unroll
            for (int t = 0; t < 5; t++) acc += mps[i2 * 15 + p + t] * w[t];
        }
        flat[idx] = fmaxf(acc, 0.f);
    }
    __syncthreads();
    {
        int w = tid >> 5, lane = tid & 31;
        float fl[11];
#pragma unroll
        for (int it = 0; it < 11; it++) fl[it] = flat[lane + it * 32];
        for (int jj = 0; jj < 32; jj++) {
            int j = w * 32 + jj;
            const float* wr = Wl1 + j * 352;
            float acc = 0.f;
#pragma unroll
            for (int it = 0; it < 11; it++) acc += fl[it] * wr[lane + it * 32];
#pragma unroll
            for (int o = 16; o; o >>= 1) acc += __shfl_xor_sync(0xffffffffu, acc, o);
            if (lane == 0) {
                float hv = fmaxf(acc + bl1[j], 0.f);
                red[j] = hv * Wl2[j];
            }
        }
    }
    __syncthreads();
    for (int off = 64; off; off >>= 1) {
        if (tid < off) red[tid] += red[tid + off];
        __syncthreads();
    }
    if (tid == 0) out[g] = red[0] + bl2[0];
}

// ---------------- launcher ----------------
extern "C" void kernel_launch(void* const* d_in, const int* in_sizes, int n_in,
                              void* d_out, int out_size) {
    const float* x   = (const float*)d_in[0];
    const int*   ei  = (const int*)  d_in[1];
    const float* W1  = (const float*)d_in[2];
    const float* b1  = (const float*)d_in[3];
    const float* W2  = (const float*)d_in[4];
    const float* b2  = (const float*)d_in[5];
    const float* W3  = (const float*)d_in[6];
    const float* b3  = (const float*)d_in[7];
    const float* Ws1 = (const float*)d_in[8];
    const float* bs1 = (const float*)d_in[9];
    const float* Ws2 = (const float*)d_in[10];
    const float* bs2 = (const float*)d_in[11];
    const float* Ws3 = (const float*)d_in[12];
    const float* bs3 = (const float*)d_in[13];
    const float* Wc1 = (const float*)d_in[14];
    const float* bc1 = (const float*)d_in[15];
    const float* Wc2 = (const float*)d_in[16];
    const float* bc2 = (const float*)d_in[17];
    const float* Wl1 = (const float*)d_in[18];
    const float* bl1 = (const float*)d_in[19];
    const float* Wl2 = (const float*)d_in[20];
    const float* bl2 = (const float*)d_in[21];
    float* out = (float*)d_out;

    float *dH, *dh, *ds0, *du, *dx1, *dx2;
    cudaGetSymbolAddress((void**)&dH,  g_H);
    cudaGetSymbolAddress((void**)&dh,  g_h);
    cudaGetSymbolAddress((void**)&ds0, g_s0);
    cudaGetSymbolAddress((void**)&du,  g_u);
    cudaGetSymbolAddress((void**)&dx1, g_x1);
    cudaGetSymbolAddress((void**)&dx2, g_x2);

    const int TB = 256;
    int gE  = (EDGES + TB - 1) / TB;
    int gW  = (NNODE * 32 + TB - 1) / TB;
    int gW8 = (NNODE * 8 + TB - 1) / TB;

    // 0: structure
    k_fillslots<<<gE, TB>>>(ei);
    // 1: gemm128 (dinv computed in epilogue)
    k_gemm<FIN><<<(NNODE + 127) / 128, 256>>>(x, W1, dH);
    // 2: agg64f #1
    k_agg64f<<<gW, TB>>>(dH, b1, Ws1, nullptr, dh, ds0, nullptr);
    // 3: gate1  <-- profiled slot this round
    k_gate<<<gW8, TB>>>(ds0, dh, bs1, dx1);
    // 4: gemm64
    k_gemm<D><<<(NNODE + 127) / 128, 256>>>(dh, W2, dH);
    // 5: agg64f #2
    k_agg64f<<<gW, TB>>>(dH, b2, Ws2, W3, dh, ds0, du);
    // 6: gate2 + h3
    k_gate2<<<gW8, TB>>>(ds0, du, dh, bs2, b3, dx2);
    // 7: s3/x3 (+ cnt reset)
    k_s3<<<gW8, TB>>>(Ws3, bs3);
    // 8: head
    k_head<<<NGRAPH, 128>>>(Wc1, bc1, Wc2, bc2, Wl1, bl1, Wl2, bl2, out);

    (void)in_sizes; (void)n_in; (void)out_size;
}